// round 14
// baseline (speedup 1.0000x reference)
#include <cuda_runtime.h>
#include <cuda_fp16.h>
#include <cstdint>

// Shapes (fixed by the problem)
#define B_   16
#define T_   12
#define N_   1000
#define F_   64
#define KC_  3
#define OUT_ 64

#define KJ_   3000            // contraction dim kj = k*1000 + j
#define KJP_  3008            // padded (47*64)
#define MP_   1024            // i padded
#define TO_   768             // t*64 + o

#define CB_   4               // batches per pipeline chunk
#define NCH_  (B_ / CB_)      // 4 chunks

// Scratch (zero-initialized at module load; pad regions never written -> stay 0)
__device__ __align__(256) float  g_ThT[KC_ * OUT_ * F_];          // tf32
__device__ __align__(256) __half g_yT[(size_t)B_ * TO_ * KJP_];   // y  fp16
__device__ __align__(256) __half g_AT[(size_t)B_ * MP_ * KJP_];   // A  fp16

__device__ __forceinline__ float to_tf32(float v) {
    uint32_t u;
    asm("cvt.rna.tf32.f32 %0, %1;" : "=r"(u) : "f"(v));
    return __uint_as_float(u);
}

__device__ __forceinline__ void cpasync16(uint32_t dst, const void* src) {
    asm volatile("cp.async.cg.shared.global [%0], [%1], 16;" :: "r"(dst), "l"(src));
}

__device__ __forceinline__ uint32_t smem_u32(const void* p) {
    uint32_t a;
    asm("{ .reg .u64 t; cvta.to.shared.u64 t, %1; cvt.u32.u64 %0, t; }"
        : "=r"(a) : "l"(p));
    return a;
}

// ---------------------------------------------------------------------------
// Kernel 0: ThT[(k*64+o)][f] = tf32(Theta[k,f,o])
// ---------------------------------------------------------------------------
__global__ __launch_bounds__(256) void k_thetaT(const float* __restrict__ Theta)
{
    for (int idx = threadIdx.x; idx < KC_ * OUT_ * F_; idx += 256) {
        const int f  = idx & 63;
        const int ko = idx >> 6;
        const int k  = ko >> 6;
        const int o  = ko & 63;
        g_ThT[idx] = to_tf32(Theta[(k * F_ + f) * OUT_ + o]);
    }
}

// ---------------------------------------------------------------------------
// Kernel 1: feature transform (mma.sync tf32), fp16 transposed output.
// One block computes ALL 192 ko rows for its (bt, j-tile). Chunked by b0.
// ---------------------------------------------------------------------------
__global__ __launch_bounds__(256) void k_featT_m(const float* __restrict__ x, int b0)
{
    __shared__ float As[192][36];
    __shared__ float Bs[128][36];

    const int j0 = blockIdx.x * 128;
    const int bt = b0 * T_ + blockIdx.y;
    const int b  = bt / T_;
    const int t  = bt % T_;

    const int tid  = threadIdx.x;
    const int lane = tid & 31;
    const int w    = tid >> 5;
    const int wm   = (w & 1) * 32;
    const int wn   = (w >> 1) * 32;

    const float* __restrict__ xp = x + (size_t)bt * N_ * F_;

    float c[3][2][4][4];
    #pragma unroll
    for (int m0i = 0; m0i < 3; m0i++)
        #pragma unroll
        for (int mt = 0; mt < 2; mt++)
            #pragma unroll
            for (int nt = 0; nt < 4; nt++)
                #pragma unroll
                for (int q = 0; q < 4; q++) c[m0i][mt][nt][q] = 0.f;

    const uint32_t as_base = smem_u32(&As[0][0]);
    const uint32_t bs_base = smem_u32(&Bs[0][0]);

    const int a_row  = lane & 15;
    const int a_col4 = (lane >> 4) * 4;
    const int b_row  = (lane & 7) + ((lane & 16) >> 1);
    const int b_col4 = ((lane >> 3) & 1) * 4;

    #pragma unroll
    for (int kt = 0; kt < 2; kt++) {
        const int f0 = kt * 32;
        #pragma unroll
        for (int l = 0; l < 6; l++) {
            int idx = tid + l * 256;
            int row = idx >> 3, c4 = (idx & 7) * 4;
            *(float4*)&As[row][c4] = *(const float4*)&g_ThT[row * F_ + f0 + c4];
        }
        #pragma unroll
        for (int l = 0; l < 4; l++) {
            int idx = tid + l * 256;
            int row = idx >> 3, c4 = (idx & 7) * 4;
            float4 v;
            if (j0 + row < N_) {
                v = *(const float4*)&xp[(size_t)(j0 + row) * F_ + f0 + c4];
                v.x = to_tf32(v.x); v.y = to_tf32(v.y);
                v.z = to_tf32(v.z); v.w = to_tf32(v.w);
            } else {
                v = make_float4(0.f, 0.f, 0.f, 0.f);
            }
            *(float4*)&Bs[row][c4] = v;
        }
        __syncthreads();

        #pragma unroll
        for (int ks = 0; ks < 4; ks++) {
            const int k0 = ks * 8;
            uint32_t bb[4][2];
            #pragma unroll
            for (int nb = 0; nb < 2; nb++) {
                uint32_t addr = bs_base +
                    (uint32_t)(((wn + nb * 16 + b_row) * 36 + k0 + b_col4) * 4);
                uint32_t r0, r1, r2, r3;
                asm volatile(
                    "ldmatrix.sync.aligned.m8n8.x4.shared.b16 {%0,%1,%2,%3}, [%4];"
                    : "=r"(r0), "=r"(r1), "=r"(r2), "=r"(r3)
                    : "r"(addr));
                bb[nb * 2][0] = r0;     bb[nb * 2][1] = r1;
                bb[nb * 2 + 1][0] = r2; bb[nb * 2 + 1][1] = r3;
            }
            #pragma unroll
            for (int m0i = 0; m0i < 3; m0i++) {
                uint32_t a[2][4];
                #pragma unroll
                for (int mt = 0; mt < 2; mt++) {
                    uint32_t addr = as_base +
                        (uint32_t)(((m0i * 64 + wm + mt * 16 + a_row) * 36 +
                                    k0 + a_col4) * 4);
                    asm volatile(
                        "ldmatrix.sync.aligned.m8n8.x4.shared.b16 {%0,%1,%2,%3}, [%4];"
                        : "=r"(a[mt][0]), "=r"(a[mt][1]), "=r"(a[mt][2]), "=r"(a[mt][3])
                        : "r"(addr));
                }
                #pragma unroll
                for (int mt = 0; mt < 2; mt++)
                    #pragma unroll
                    for (int nt = 0; nt < 4; nt++)
                        asm volatile(
                            "mma.sync.aligned.m16n8k8.row.col.f32.tf32.tf32.f32 "
                            "{%0,%1,%2,%3}, {%4,%5,%6,%7}, {%8,%9}, {%0,%1,%2,%3};"
                            : "+f"(c[m0i][mt][nt][0]), "+f"(c[m0i][mt][nt][1]),
                              "+f"(c[m0i][mt][nt][2]), "+f"(c[m0i][mt][nt][3])
                            : "r"(a[mt][0]), "r"(a[mt][1]), "r"(a[mt][2]), "r"(a[mt][3]),
                              "r"(bb[nt][0]), "r"(bb[nt][1]));
            }
        }
        __syncthreads();
    }

    const int gid = lane >> 2;
    const int tig = lane & 3;
    #pragma unroll
    for (int m0i = 0; m0i < 3; m0i++) {
        #pragma unroll
        for (int mt = 0; mt < 2; mt++) {
            #pragma unroll
            for (int half = 0; half < 2; half++) {
                const int ko = m0i * 64 + wm + mt * 16 + half * 8 + gid;
                const int k  = ko >> 6;
                const int o  = ko & 63;
                __half* __restrict__ dst =
                    g_yT + ((size_t)b * TO_ + t * OUT_ + o) * KJP_ + (size_t)k * N_;
                #pragma unroll
                for (int nt = 0; nt < 4; nt++) {
                    const int j = j0 + wn + nt * 8 + tig * 2;
                    if (j < N_) {
                        __half2 v;
                        v.x = __float2half_rn(c[m0i][mt][nt][half * 2 + 0]);
                        v.y = __float2half_rn(c[m0i][mt][nt][half * 2 + 1]);
                        *(__half2*)&dst[j] = v;
                    }
                }
            }
        }
    }
}

// ---------------------------------------------------------------------------
// Kernel 2: AT[b][i][kj] = fp16( cheb[kj,i] * SAtt[b, kj%1000, i] ). Chunked.
// ---------------------------------------------------------------------------
__global__ __launch_bounds__(256) void k_buildA(
    const float* __restrict__ SAtt,
    const float* __restrict__ cheb, int b0)
{
    __shared__ float buf[256][33];
    const int b    = b0 + blockIdx.z;
    const int i0   = blockIdx.y * 32;
    const int kjc  = blockIdx.x * 256;
    const int lane = threadIdx.x & 31;
    const int w    = threadIdx.x >> 5;
    const int i    = i0 + lane;

    const float* __restrict__ sb = SAtt + (size_t)b * N_ * N_;

    #pragma unroll 4
    for (int r = 0; r < 32; r++) {
        int kj = kjc + w * 32 + r;
        float v = 0.f;
        if (kj < KJ_ && i < N_) {
            int k = (kj >= 2000) ? 2 : (kj >= 1000 ? 1 : 0);
            int j = kj - k * 1000;
            v = __ldg(cheb + (size_t)kj * N_ + i) * __ldg(sb + (size_t)j * N_ + i);
        }
        buf[w * 32 + r][lane] = v;
    }
    __syncthreads();

    #pragma unroll
    for (int rr = 0; rr < 4; rr++) {
        int iw = i0 + w * 4 + rr;
        if (iw < N_) {
            __half* __restrict__ outp = g_AT + ((size_t)b * MP_ + iw) * KJP_;
            #pragma unroll
            for (int c2 = 0; c2 < 4; c2++) {
                int kj = kjc + c2 * 64 + lane * 2;
                if (kj < KJ_) {
                    __half2 hv;
                    hv.x = __float2half_rn(buf[c2 * 64 + lane * 2    ][w * 4 + rr]);
                    hv.y = __float2half_rn(buf[c2 * 64 + lane * 2 + 1][w * 4 + rr]);
                    *(__half2*)&outp[kj] = hv;
                }
            }
        }
    }
}

// ---------------------------------------------------------------------------
// Kernel 3: spatial GEMM (R12 proven config), chunked by b0.
// ---------------------------------------------------------------------------
#define SBK    64
#define NTILE  (KJP_ / SBK)          // 47
#define BNX    256
#define ROWH   72
#define A_STGH (128 * ROWH)
#define B_STGH (BNX * ROWH)
#define STG3   3

__global__ __launch_bounds__(512) void k_spatial_fp16k(float* __restrict__ out, int b0)
{
    extern __shared__ __half sm[];
    __half* Asm = sm;
    __half* Bsm = sm + STG3 * A_STGH;

    const int b  = b0 + blockIdx.z;
    const int i0 = blockIdx.y * 128;
    const int n0 = blockIdx.x * BNX;

    const int tid  = threadIdx.x;
    const int lane = tid & 31;
    const int w    = tid >> 5;
    const int im   = (w & 1) * 64;
    const int in_  = (w >> 1) * 32;

    const __half* __restrict__ pA = g_AT + ((size_t)b * MP_ + i0) * KJP_;
    const __half* __restrict__ pB = g_yT + ((size_t)b * TO_ + n0) * KJP_;

    float c[4][4][4];
    #pragma unroll
    for (int mt = 0; mt < 4; mt++)
        #pragma unroll
        for (int nt = 0; nt < 4; nt++)
            #pragma unroll
            for (int q = 0; q < 4; q++) c[mt][nt][q] = 0.f;

    const uint32_t as_base = smem_u32(Asm);
    const uint32_t bs_base = smem_u32(Bsm);

    const int ld_row = tid >> 3;
    const int ld_h0  = (tid & 7) * 8;

    const int a_row = lane & 15;
    const int a_k8  = lane >> 4;
    const int b_row = (lane & 7) + ((lane & 16) >> 1);
    const int b_k8  = (lane >> 3) & 1;

    #define LOAD_TILE(p, s) do {                                                \
        const uint32_t ao = as_base + (uint32_t)((s) * A_STGH * 2);             \
        const uint32_t bo = bs_base + (uint32_t)((s) * B_STGH * 2);             \
        _Pragma("unroll")                                                       \
        for (int l = 0; l < 2; l++) {                                           \
            const int row = ld_row + l * 64;                                    \
            cpasync16(ao + (uint32_t)((row * ROWH + ld_h0) * 2),                \
                      pA + (size_t)row * KJP_ + (p) + ld_h0);                   \
        }                                                                       \
        _Pragma("unroll")                                                       \
        for (int l = 0; l < 4; l++) {                                           \
            const int row = ld_row + l * 64;                                    \
            cpasync16(bo + (uint32_t)((row * ROWH + ld_h0) * 2),                \
                      pB + (size_t)row * KJP_ + (p) + ld_h0);                   \
        }                                                                       \
        asm volatile("cp.async.commit_group;");                                 \
    } while (0)

    LOAD_TILE(0, 0);
    LOAD_TILE(SBK, 1);

    for (int pc = 0; pc < NTILE; pc++) {
        const int cur = pc % STG3;

        if (pc < NTILE - 1) asm volatile("cp.async.wait_group 1;");
        else                asm volatile("cp.async.wait_group 0;");
        __syncthreads();

        if (pc + 2 < NTILE) LOAD_TILE((pc + 2) * SBK, (pc + 2) % STG3);

        const uint32_t sA = as_base + (uint32_t)(cur * A_STGH * 2);
        const uint32_t sB = bs_base + (uint32_t)(cur * B_STGH * 2);

        #pragma unroll
        for (int ks = 0; ks < 4; ks++) {
            const int kb = ks * 16;

            uint32_t a[4][4];
            #pragma unroll
            for (int mt = 0; mt < 4; mt++) {
                const uint32_t off =
                    (uint32_t)(((im + mt * 16 + a_row) * ROWH + kb + a_k8 * 8) * 2);
                asm volatile(
                    "ldmatrix.sync.aligned.m8n8.x4.shared.b16 {%0,%1,%2,%3}, [%4];"
                    : "=r"(a[mt][0]), "=r"(a[mt][1]), "=r"(a[mt][2]), "=r"(a[mt][3])
                    : "r"(sA + off));
            }
            uint32_t bb[4][2];
            #pragma unroll
            for (int nb = 0; nb < 2; nb++) {
                const uint32_t off =
                    (uint32_t)(((in_ + nb * 16 + b_row) * ROWH + kb + b_k8 * 8) * 2);
                uint32_t r0, r1, r2, r3;
                asm volatile(
                    "ldmatrix.sync.aligned.m8n8.x4.shared.b16 {%0,%1,%2,%3}, [%4];"
                    : "=r"(r0), "=r"(r1), "=r"(r2), "=r"(r3)
                    : "r"(sB + off));
                bb[nb * 2][0] = r0;     bb[nb * 2][1] = r1;
                bb[nb * 2 + 1][0] = r2; bb[nb * 2 + 1][1] = r3;
            }
            #pragma unroll
            for (int mt = 0; mt < 4; mt++)
                #pragma unroll
                for (int nt = 0; nt < 4; nt++)
                    asm volatile(
                        "mma.sync.aligned.m16n8k16.row.col.f32.f16.f16.f32 "
                        "{%0,%1,%2,%3}, {%4,%5,%6,%7}, {%8,%9}, {%0,%1,%2,%3};"
                        : "+f"(c[mt][nt][0]), "+f"(c[mt][nt][1]),
                          "+f"(c[mt][nt][2]), "+f"(c[mt][nt][3])
                        : "r"(a[mt][0]), "r"(a[mt][1]), "r"(a[mt][2]), "r"(a[mt][3]),
                          "r"(bb[nt][0]), "r"(bb[nt][1]));
        }
    }

    const int gid = lane >> 2;
    const int tig = lane & 3;
    const int t   = (n0 + in_) >> 6;
    const int o0  = (n0 + in_) & 63;
    #pragma unroll
    for (int mt = 0; mt < 4; mt++) {
        #pragma unroll
        for (int half = 0; half < 2; half++) {
            const int i = i0 + im + mt * 16 + half * 8 + gid;
            if (i < N_) {
                float* __restrict__ dst =
                    out + (size_t)b * (T_ * N_ * OUT_) + (size_t)t * (N_ * OUT_) +
                    (size_t)i * OUT_ + o0;
                #pragma unroll
                for (int nt = 0; nt < 4; nt++) {
                    const int o = nt * 8 + tig * 2;
                    float2 v;
                    v.x = fmaxf(c[mt][nt][half * 2 + 0], 0.f);
                    v.y = fmaxf(c[mt][nt][half * 2 + 1], 0.f);
                    *(float2*)&dst[o] = v;
                }
            }
        }
    }
}

// ---------------------------------------------------------------------------
// Launch: batch-chunked pipeline. Prep chunk c runs on a side stream while
// spatial chunks stream on two streams (each gated on its prep event).
// Streams/events created once on the first (non-captured) call; fork-join
// event pattern is graph-capture legal.
// ---------------------------------------------------------------------------
extern "C" void kernel_launch(void* const* d_in, const int* in_sizes, int n_in,
                              void* d_out, int out_size)
{
    const float* x     = (const float*)d_in[0];
    const float* SAtt  = (const float*)d_in[1];
    const float* cheb  = (const float*)d_in[2];
    const float* Theta = (const float*)d_in[3];
    float* out = (float*)d_out;

    static cudaStream_t sPrep = nullptr, sSp2 = nullptr;
    static cudaEvent_t  eP[NCH_], eJoin;
    if (!sPrep) {
        cudaStreamCreateWithFlags(&sPrep, cudaStreamNonBlocking);
        cudaStreamCreateWithFlags(&sSp2,  cudaStreamNonBlocking);
        for (int c = 0; c < NCH_; c++)
            cudaEventCreateWithFlags(&eP[c], cudaEventDisableTiming);
        cudaEventCreateWithFlags(&eJoin, cudaEventDisableTiming);
    }

    const int smem_sp = STG3 * (A_STGH + B_STGH) * 2;   // 165888 B
    cudaFuncSetAttribute(k_spatial_fp16k,
                         cudaFuncAttributeMaxDynamicSharedMemorySize, smem_sp);

    const dim3 gFeat(8, CB_ * T_);
    const dim3 gBld(12, 32, CB_);
    const dim3 gSp(TO_ / BNX, MP_ / 128, CB_);

    // chunk 0 prep on the main stream
    k_thetaT<<<1, 256>>>(Theta);
    k_featT_m<<<gFeat, 256>>>(x, 0);
    k_buildA<<<gBld, 256>>>(SAtt, cheb, 0);
    cudaEventRecord(eP[0], 0);

    // remaining prep chunks, serial on sPrep (forked from main stream)
    cudaStreamWaitEvent(sPrep, eP[0], 0);
    for (int c = 1; c < NCH_; c++) {
        k_featT_m<<<gFeat, 256, 0, sPrep>>>(x, c * CB_);
        k_buildA<<<gBld, 256, 0, sPrep>>>(SAtt, cheb, c * CB_);
        cudaEventRecord(eP[c], sPrep);
    }

    // spatial chunks: alternate main stream / sSp2, each gated on its prep
    k_spatial_fp16k<<<gSp, 512, smem_sp>>>(out, 0);

    cudaStreamWaitEvent(sSp2, eP[1], 0);
    k_spatial_fp16k<<<gSp, 512, smem_sp, sSp2>>>(out, 1 * CB_);

    cudaStreamWaitEvent(0, eP[2], 0);
    k_spatial_fp16k<<<gSp, 512, smem_sp>>>(out, 2 * CB_);

    cudaStreamWaitEvent(sSp2, eP[3], 0);
    k_spatial_fp16k<<<gSp, 512, smem_sp, sSp2>>>(out, 3 * CB_);

    // join side streams back into the main stream
    cudaEventRecord(eJoin, sSp2);
    cudaStreamWaitEvent(0, eJoin, 0);
}

// round 16
// speedup vs baseline: 1.0660x; 1.0660x over previous
#include <cuda_runtime.h>
#include <cuda_fp16.h>
#include <cstdint>

// Shapes (fixed by the problem)
#define B_   16
#define T_   12
#define N_   1000
#define F_   64
#define KC_  3
#define OUT_ 64

#define KJ_   3000            // contraction dim kj = k*1000 + j
#define KJP_  3008            // padded (47*64)
#define MP_   1024            // i padded
#define TO_   768             // t*64 + o

// Scratch (zero-initialized at module load; pad regions never written -> stay 0)
__device__ __align__(256) float  g_ThT[KC_ * OUT_ * F_];          // tf32
__device__ __align__(256) __half g_yT[(size_t)B_ * TO_ * KJP_];   // y  fp16
__device__ __align__(256) __half g_AT[(size_t)B_ * MP_ * KJP_];   // A  fp16

__device__ __forceinline__ float to_tf32(float v) {
    uint32_t u;
    asm("cvt.rna.tf32.f32 %0, %1;" : "=r"(u) : "f"(v));
    return __uint_as_float(u);
}

__device__ __forceinline__ void cpasync16(uint32_t dst, const void* src) {
    asm volatile("cp.async.cg.shared.global [%0], [%1], 16;" :: "r"(dst), "l"(src));
}

__device__ __forceinline__ uint32_t smem_u32(const void* p) {
    uint32_t a;
    asm("{ .reg .u64 t; cvta.to.shared.u64 t, %1; cvt.u32.u64 %0, t; }"
        : "=r"(a) : "l"(p));
    return a;
}

// ---------------------------------------------------------------------------
// Kernel 0: ThT[(k*64+o)][f] = tf32(Theta[k,f,o])
// ---------------------------------------------------------------------------
__global__ __launch_bounds__(256) void k_thetaT(const float* __restrict__ Theta)
{
    for (int idx = threadIdx.x; idx < KC_ * OUT_ * F_; idx += 256) {
        const int f  = idx & 63;
        const int ko = idx >> 6;
        const int k  = ko >> 6;
        const int o  = ko & 63;
        g_ThT[idx] = to_tf32(Theta[(k * F_ + f) * OUT_ + o]);
    }
}

// ---------------------------------------------------------------------------
// Kernel 1: feature transform (mma.sync tf32), fp16 transposed output.
// One block computes ALL 192 ko rows for its (bt, j-tile).
// ---------------------------------------------------------------------------
__global__ __launch_bounds__(256) void k_featT_m(const float* __restrict__ x)
{
    __shared__ float As[192][36];
    __shared__ float Bs[128][36];

    const int j0 = blockIdx.x * 128;
    const int bt = blockIdx.y;
    const int b  = bt / T_;
    const int t  = bt % T_;

    const int tid  = threadIdx.x;
    const int lane = tid & 31;
    const int w    = tid >> 5;
    const int wm   = (w & 1) * 32;
    const int wn   = (w >> 1) * 32;

    const float* __restrict__ xp = x + (size_t)bt * N_ * F_;

    float c[3][2][4][4];
    #pragma unroll
    for (int m0i = 0; m0i < 3; m0i++)
        #pragma unroll
        for (int mt = 0; mt < 2; mt++)
            #pragma unroll
            for (int nt = 0; nt < 4; nt++)
                #pragma unroll
                for (int q = 0; q < 4; q++) c[m0i][mt][nt][q] = 0.f;

    const uint32_t as_base = smem_u32(&As[0][0]);
    const uint32_t bs_base = smem_u32(&Bs[0][0]);

    const int a_row  = lane & 15;
    const int a_col4 = (lane >> 4) * 4;
    const int b_row  = (lane & 7) + ((lane & 16) >> 1);
    const int b_col4 = ((lane >> 3) & 1) * 4;

    #pragma unroll
    for (int kt = 0; kt < 2; kt++) {
        const int f0 = kt * 32;
        #pragma unroll
        for (int l = 0; l < 6; l++) {
            int idx = tid + l * 256;
            int row = idx >> 3, c4 = (idx & 7) * 4;
            *(float4*)&As[row][c4] = *(const float4*)&g_ThT[row * F_ + f0 + c4];
        }
        #pragma unroll
        for (int l = 0; l < 4; l++) {
            int idx = tid + l * 256;
            int row = idx >> 3, c4 = (idx & 7) * 4;
            float4 v;
            if (j0 + row < N_) {
                v = *(const float4*)&xp[(size_t)(j0 + row) * F_ + f0 + c4];
                v.x = to_tf32(v.x); v.y = to_tf32(v.y);
                v.z = to_tf32(v.z); v.w = to_tf32(v.w);
            } else {
                v = make_float4(0.f, 0.f, 0.f, 0.f);
            }
            *(float4*)&Bs[row][c4] = v;
        }
        __syncthreads();

        #pragma unroll
        for (int ks = 0; ks < 4; ks++) {
            const int k0 = ks * 8;
            uint32_t bb[4][2];
            #pragma unroll
            for (int nb = 0; nb < 2; nb++) {
                uint32_t addr = bs_base +
                    (uint32_t)(((wn + nb * 16 + b_row) * 36 + k0 + b_col4) * 4);
                uint32_t r0, r1, r2, r3;
                asm volatile(
                    "ldmatrix.sync.aligned.m8n8.x4.shared.b16 {%0,%1,%2,%3}, [%4];"
                    : "=r"(r0), "=r"(r1), "=r"(r2), "=r"(r3)
                    : "r"(addr));
                bb[nb * 2][0] = r0;     bb[nb * 2][1] = r1;
                bb[nb * 2 + 1][0] = r2; bb[nb * 2 + 1][1] = r3;
            }
            #pragma unroll
            for (int m0i = 0; m0i < 3; m0i++) {
                uint32_t a[2][4];
                #pragma unroll
                for (int mt = 0; mt < 2; mt++) {
                    uint32_t addr = as_base +
                        (uint32_t)(((m0i * 64 + wm + mt * 16 + a_row) * 36 +
                                    k0 + a_col4) * 4);
                    asm volatile(
                        "ldmatrix.sync.aligned.m8n8.x4.shared.b16 {%0,%1,%2,%3}, [%4];"
                        : "=r"(a[mt][0]), "=r"(a[mt][1]), "=r"(a[mt][2]), "=r"(a[mt][3])
                        : "r"(addr));
                }
                #pragma unroll
                for (int mt = 0; mt < 2; mt++)
                    #pragma unroll
                    for (int nt = 0; nt < 4; nt++)
                        asm volatile(
                            "mma.sync.aligned.m16n8k8.row.col.f32.tf32.tf32.f32 "
                            "{%0,%1,%2,%3}, {%4,%5,%6,%7}, {%8,%9}, {%0,%1,%2,%3};"
                            : "+f"(c[m0i][mt][nt][0]), "+f"(c[m0i][mt][nt][1]),
                              "+f"(c[m0i][mt][nt][2]), "+f"(c[m0i][mt][nt][3])
                            : "r"(a[mt][0]), "r"(a[mt][1]), "r"(a[mt][2]), "r"(a[mt][3]),
                              "r"(bb[nt][0]), "r"(bb[nt][1]));
            }
        }
        __syncthreads();
    }

    const int gid = lane >> 2;
    const int tig = lane & 3;
    #pragma unroll
    for (int m0i = 0; m0i < 3; m0i++) {
        #pragma unroll
        for (int mt = 0; mt < 2; mt++) {
            #pragma unroll
            for (int half = 0; half < 2; half++) {
                const int ko = m0i * 64 + wm + mt * 16 + half * 8 + gid;
                const int k  = ko >> 6;
                const int o  = ko & 63;
                __half* __restrict__ dst =
                    g_yT + ((size_t)b * TO_ + t * OUT_ + o) * KJP_ + (size_t)k * N_;
                #pragma unroll
                for (int nt = 0; nt < 4; nt++) {
                    const int j = j0 + wn + nt * 8 + tig * 2;
                    if (j < N_) {
                        __half2 v;
                        v.x = __float2half_rn(c[m0i][mt][nt][half * 2 + 0]);
                        v.y = __float2half_rn(c[m0i][mt][nt][half * 2 + 1]);
                        *(__half2*)&dst[j] = v;
                    }
                }
            }
        }
    }
}

// ---------------------------------------------------------------------------
// Kernel 2: AT[b][i][kj] = fp16( cheb[kj,i] * SAtt[b, kj%1000, i] )
// Per-b grid; half2 output stores.
// ---------------------------------------------------------------------------
__global__ __launch_bounds__(256) void k_buildA(
    const float* __restrict__ SAtt,
    const float* __restrict__ cheb)
{
    __shared__ float buf[256][33];
    const int b    = blockIdx.z;
    const int i0   = blockIdx.y * 32;
    const int kjc  = blockIdx.x * 256;
    const int lane = threadIdx.x & 31;
    const int w    = threadIdx.x >> 5;
    const int i    = i0 + lane;

    const float* __restrict__ sb = SAtt + (size_t)b * N_ * N_;

    #pragma unroll 4
    for (int r = 0; r < 32; r++) {
        int kj = kjc + w * 32 + r;
        float v = 0.f;
        if (kj < KJ_ && i < N_) {
            int k = (kj >= 2000) ? 2 : (kj >= 1000 ? 1 : 0);
            int j = kj - k * 1000;
            v = __ldg(cheb + (size_t)kj * N_ + i) * __ldg(sb + (size_t)j * N_ + i);
        }
        buf[w * 32 + r][lane] = v;
    }
    __syncthreads();

    #pragma unroll
    for (int rr = 0; rr < 4; rr++) {
        int iw = i0 + w * 4 + rr;
        if (iw < N_) {
            __half* __restrict__ outp = g_AT + ((size_t)b * MP_ + iw) * KJP_;
            #pragma unroll
            for (int c2 = 0; c2 < 4; c2++) {
                int kj = kjc + c2 * 64 + lane * 2;
                if (kj < KJ_) {
                    __half2 hv;
                    hv.x = __float2half_rn(buf[c2 * 64 + lane * 2    ][w * 4 + rr]);
                    hv.y = __float2half_rn(buf[c2 * 64 + lane * 2 + 1][w * 4 + rr]);
                    *(__half2*)&outp[kj] = hv;
                }
            }
        }
    }
}

// ---------------------------------------------------------------------------
// Kernel 3: spatial GEMM, fp16 m16n8k16, CTA 128x128, 256 thr / 8 warps,
// warp tile 64x32 (2m x 4n), BK=64, 2-stage cp.async ring, 2 CTAs/SM.
// Cross-CTA overlap absorbs per-tile barrier/wait stalls.
//   D[b][i][to] = relu( sum_kj AT[b][i][kj] * yT[b][to][kj] )
// ---------------------------------------------------------------------------
#define SBK    64
#define NTILE  (KJP_ / SBK)          // 47
#define BNX    128
#define ROWH   72                    // halfs per smem row (144B, 16B-pad)
#define A_STGH (128 * ROWH)          // 18 KB
#define B_STGH (BNX * ROWH)          // 18 KB
#define STG2   2

__global__ __launch_bounds__(256, 2) void k_spatial_2c(float* __restrict__ out)
{
    extern __shared__ __half sm[];
    __half* Asm = sm;                        // [2][128][72]
    __half* Bsm = sm + STG2 * A_STGH;        // [2][128][72]

    const int b  = blockIdx.z;
    const int i0 = blockIdx.y * 128;
    const int n0 = blockIdx.x * BNX;

    const int tid  = threadIdx.x;
    const int lane = tid & 31;
    const int w    = tid >> 5;            // 0..7
    const int im   = (w & 1) * 64;        // 2 m-strips
    const int in_  = (w >> 1) * 32;       // 4 n-strips

    const __half* __restrict__ pA = g_AT + ((size_t)b * MP_ + i0) * KJP_;
    const __half* __restrict__ pB = g_yT + ((size_t)b * TO_ + n0) * KJP_;

    float c[4][4][4];
    #pragma unroll
    for (int mt = 0; mt < 4; mt++)
        #pragma unroll
        for (int nt = 0; nt < 4; nt++)
            #pragma unroll
            for (int q = 0; q < 4; q++) c[mt][nt][q] = 0.f;

    const uint32_t as_base = smem_u32(Asm);
    const uint32_t bs_base = smem_u32(Bsm);

    // loader: 128 rows x 64 halfs per operand = 1024 chunks; 4/thread each op
    const int ld_row = tid >> 3;          // 0..31 (+32*l)
    const int ld_h0  = (tid & 7) * 8;     // half offset 0..56

    const int a_row = lane & 15;
    const int a_k8  = lane >> 4;
    const int b_row = (lane & 7) + ((lane & 16) >> 1);
    const int b_k8  = (lane >> 3) & 1;

    #define LOAD_TILE(p, s) do {                                                \
        const uint32_t ao = as_base + (uint32_t)((s) * A_STGH * 2);             \
        const uint32_t bo = bs_base + (uint32_t)((s) * B_STGH * 2);             \
        _Pragma("unroll")                                                       \
        for (int l = 0; l < 4; l++) {                                           \
            const int row = ld_row + l * 32;                                    \
            cpasync16(ao + (uint32_t)((row * ROWH + ld_h0) * 2),                \
                      pA + (size_t)row * KJP_ + (p) + ld_h0);                   \
            cpasync16(bo + (uint32_t)((row * ROWH + ld_h0) * 2),                \
                      pB + (size_t)row * KJP_ + (p) + ld_h0);                   \
        }                                                                       \
        asm volatile("cp.async.commit_group;");                                 \
    } while (0)

    // prologue: tile 0 -> stage 0
    LOAD_TILE(0, 0);

    for (int pc = 0; pc < NTILE; pc++) {
        const int cur = pc & 1;

        // only outstanding group is tile pc
        asm volatile("cp.async.wait_group 0;");
        __syncthreads();

        // prefetch tile pc+1 into the other stage (overlaps compute below;
        // its stage's prior readers all passed the barrier above)
        if (pc + 1 < NTILE) LOAD_TILE((pc + 1) * SBK, cur ^ 1);

        const uint32_t sA = as_base + (uint32_t)(cur * A_STGH * 2);
        const uint32_t sB = bs_base + (uint32_t)(cur * B_STGH * 2);

        #pragma unroll
        for (int ks = 0; ks < 4; ks++) {
            const int kb = ks * 16;

            uint32_t a[4][4];
            #pragma unroll
            for (int mt = 0; mt < 4; mt++) {
                const uint32_t off =
                    (uint32_t)(((im + mt * 16 + a_row) * ROWH + kb + a_k8 * 8) * 2);
                asm volatile(
                    "ldmatrix.sync.aligned.m8n8.x4.shared.b16 {%0,%1,%2,%3}, [%4];"
                    : "=r"(a[mt][0]), "=r"(a[mt][1]), "=r"(a[mt][2]), "=r"(a[mt][3])
                    : "r"(sA + off));
            }
            uint32_t bb[4][2];
            #pragma unroll
            for (int nb = 0; nb < 2; nb++) {
                const uint32_t off =
                    (uint32_t)(((in_ + nb * 16 + b_row) * ROWH + kb + b_k8 * 8) * 2);
                uint32_t r0, r1, r2, r3;
                asm volatile(
                    "ldmatrix.sync.aligned.m8n8.x4.shared.b16 {%0,%1,%2,%3}, [%4];"
                    : "=r"(r0), "=r"(r1), "=r"(r2), "=r"(r3)
                    : "r"(sB + off));
                bb[nb * 2][0] = r0;     bb[nb * 2][1] = r1;
                bb[nb * 2 + 1][0] = r2; bb[nb * 2 + 1][1] = r3;
            }
            #pragma unroll
            for (int mt = 0; mt < 4; mt++)
                #pragma unroll
                for (int nt = 0; nt < 4; nt++)
                    asm volatile(
                        "mma.sync.aligned.m16n8k16.row.col.f32.f16.f16.f32 "
                        "{%0,%1,%2,%3}, {%4,%5,%6,%7}, {%8,%9}, {%0,%1,%2,%3};"
                        : "+f"(c[mt][nt][0]), "+f"(c[mt][nt][1]),
                          "+f"(c[mt][nt][2]), "+f"(c[mt][nt][3])
                        : "r"(a[mt][0]), "r"(a[mt][1]), "r"(a[mt][2]), "r"(a[mt][3]),
                          "r"(bb[nt][0]), "r"(bb[nt][1]));
        }
        __syncthreads();
    }

    // Epilogue with fused relu. Warp n-extent 32, 32-aligned -> t const.
    const int gid = lane >> 2;
    const int tig = lane & 3;
    const int t   = (n0 + in_) >> 6;
    const int o0  = (n0 + in_) & 63;
    #pragma unroll
    for (int mt = 0; mt < 4; mt++) {
        #pragma unroll
        for (int half = 0; half < 2; half++) {
            const int i = i0 + im + mt * 16 + half * 8 + gid;
            if (i < N_) {
                float* __restrict__ dst =
                    out + (size_t)b * (T_ * N_ * OUT_) + (size_t)t * (N_ * OUT_) +
                    (size_t)i * OUT_ + o0;
                #pragma unroll
                for (int nt = 0; nt < 4; nt++) {
                    const int o = nt * 8 + tig * 2;
                    float2 v;
                    v.x = fmaxf(c[mt][nt][half * 2 + 0], 0.f);
                    v.y = fmaxf(c[mt][nt][half * 2 + 1], 0.f);
                    *(float2*)&dst[o] = v;
                }
            }
        }
    }
}

// ---------------------------------------------------------------------------
// Launch (single stream — R12 structure)
// ---------------------------------------------------------------------------
extern "C" void kernel_launch(void* const* d_in, const int* in_sizes, int n_in,
                              void* d_out, int out_size)
{
    const float* x     = (const float*)d_in[0];
    const float* SAtt  = (const float*)d_in[1];
    const float* cheb  = (const float*)d_in[2];
    const float* Theta = (const float*)d_in[3];
    float* out = (float*)d_out;

    const int smem_sp = STG2 * (A_STGH + B_STGH) * 2;   // 73728 B
    cudaFuncSetAttribute(k_spatial_2c,
                         cudaFuncAttributeMaxDynamicSharedMemorySize, smem_sp);

    k_thetaT<<<1, 256>>>(Theta);
    k_featT_m<<<dim3(8, B_ * T_), 256>>>(x);
    k_buildA<<<dim3(12, 32, B_), 256>>>(SAtt, cheb);
    k_spatial_2c<<<dim3(TO_ / BNX, MP_ / 128, B_), 256, smem_sp>>>(out);
}

// round 17
// speedup vs baseline: 1.1104x; 1.0416x over previous
#include <cuda_runtime.h>
#include <cuda_fp16.h>
#include <cstdint>

// Shapes (fixed by the problem)
#define B_   16
#define T_   12
#define N_   1000
#define F_   64
#define KC_  3
#define OUT_ 64

#define KJ_   3000            // contraction dim kj = k*1000 + j
#define KJP_  3008            // padded (47*64)
#define MP_   1024            // i padded
#define TO_   768             // t*64 + o

// Scratch (zero-initialized at module load; pad regions never written -> stay 0)
__device__ __align__(256) float  g_ThT[KC_ * OUT_ * F_];          // tf32
__device__ __align__(256) __half g_yT[(size_t)B_ * TO_ * KJP_];   // y[b][to][kj]
__device__ __align__(256) __half g_AT[(size_t)B_ * KJP_ * MP_];   // A[b][kj][i] (!)

__device__ __forceinline__ float to_tf32(float v) {
    uint32_t u;
    asm("cvt.rna.tf32.f32 %0, %1;" : "=r"(u) : "f"(v));
    return __uint_as_float(u);
}

__device__ __forceinline__ void cpasync16(uint32_t dst, const void* src) {
    asm volatile("cp.async.cg.shared.global [%0], [%1], 16;" :: "r"(dst), "l"(src));
}

__device__ __forceinline__ uint32_t smem_u32(const void* p) {
    uint32_t a;
    asm("{ .reg .u64 t; cvta.to.shared.u64 t, %1; cvt.u32.u64 %0, t; }"
        : "=r"(a) : "l"(p));
    return a;
}

// ---------------------------------------------------------------------------
// Kernel 0: ThT[(k*64+o)][f] = tf32(Theta[k,f,o])
// ---------------------------------------------------------------------------
__global__ __launch_bounds__(256) void k_thetaT(const float* __restrict__ Theta)
{
    for (int idx = threadIdx.x; idx < KC_ * OUT_ * F_; idx += 256) {
        const int f  = idx & 63;
        const int ko = idx >> 6;
        const int k  = ko >> 6;
        const int o  = ko & 63;
        g_ThT[idx] = to_tf32(Theta[(k * F_ + f) * OUT_ + o]);
    }
}

// ---------------------------------------------------------------------------
// Kernel 1: feature transform (mma.sync tf32), fp16 transposed output.
// One block computes ALL 192 ko rows for its (bt, j-tile).
// ---------------------------------------------------------------------------
__global__ __launch_bounds__(256) void k_featT_m(const float* __restrict__ x)
{
    __shared__ float As[192][36];
    __shared__ float Bs[128][36];

    const int j0 = blockIdx.x * 128;
    const int bt = blockIdx.y;
    const int b  = bt / T_;
    const int t  = bt % T_;

    const int tid  = threadIdx.x;
    const int lane = tid & 31;
    const int w    = tid >> 5;
    const int wm   = (w & 1) * 32;
    const int wn   = (w >> 1) * 32;

    const float* __restrict__ xp = x + (size_t)bt * N_ * F_;

    float c[3][2][4][4];
    #pragma unroll
    for (int m0i = 0; m0i < 3; m0i++)
        #pragma unroll
        for (int mt = 0; mt < 2; mt++)
            #pragma unroll
            for (int nt = 0; nt < 4; nt++)
                #pragma unroll
                for (int q = 0; q < 4; q++) c[m0i][mt][nt][q] = 0.f;

    const uint32_t as_base = smem_u32(&As[0][0]);
    const uint32_t bs_base = smem_u32(&Bs[0][0]);

    const int a_row  = lane & 15;
    const int a_col4 = (lane >> 4) * 4;
    const int b_row  = (lane & 7) + ((lane & 16) >> 1);
    const int b_col4 = ((lane >> 3) & 1) * 4;

    #pragma unroll
    for (int kt = 0; kt < 2; kt++) {
        const int f0 = kt * 32;
        #pragma unroll
        for (int l = 0; l < 6; l++) {
            int idx = tid + l * 256;
            int row = idx >> 3, c4 = (idx & 7) * 4;
            *(float4*)&As[row][c4] = *(const float4*)&g_ThT[row * F_ + f0 + c4];
        }
        #pragma unroll
        for (int l = 0; l < 4; l++) {
            int idx = tid + l * 256;
            int row = idx >> 3, c4 = (idx & 7) * 4;
            float4 v;
            if (j0 + row < N_) {
                v = *(const float4*)&xp[(size_t)(j0 + row) * F_ + f0 + c4];
                v.x = to_tf32(v.x); v.y = to_tf32(v.y);
                v.z = to_tf32(v.z); v.w = to_tf32(v.w);
            } else {
                v = make_float4(0.f, 0.f, 0.f, 0.f);
            }
            *(float4*)&Bs[row][c4] = v;
        }
        __syncthreads();

        #pragma unroll
        for (int ks = 0; ks < 4; ks++) {
            const int k0 = ks * 8;
            uint32_t bb[4][2];
            #pragma unroll
            for (int nb = 0; nb < 2; nb++) {
                uint32_t addr = bs_base +
                    (uint32_t)(((wn + nb * 16 + b_row) * 36 + k0 + b_col4) * 4);
                uint32_t r0, r1, r2, r3;
                asm volatile(
                    "ldmatrix.sync.aligned.m8n8.x4.shared.b16 {%0,%1,%2,%3}, [%4];"
                    : "=r"(r0), "=r"(r1), "=r"(r2), "=r"(r3)
                    : "r"(addr));
                bb[nb * 2][0] = r0;     bb[nb * 2][1] = r1;
                bb[nb * 2 + 1][0] = r2; bb[nb * 2 + 1][1] = r3;
            }
            #pragma unroll
            for (int m0i = 0; m0i < 3; m0i++) {
                uint32_t a[2][4];
                #pragma unroll
                for (int mt = 0; mt < 2; mt++) {
                    uint32_t addr = as_base +
                        (uint32_t)(((m0i * 64 + wm + mt * 16 + a_row) * 36 +
                                    k0 + a_col4) * 4);
                    asm volatile(
                        "ldmatrix.sync.aligned.m8n8.x4.shared.b16 {%0,%1,%2,%3}, [%4];"
                        : "=r"(a[mt][0]), "=r"(a[mt][1]), "=r"(a[mt][2]), "=r"(a[mt][3])
                        : "r"(addr));
                }
                #pragma unroll
                for (int mt = 0; mt < 2; mt++)
                    #pragma unroll
                    for (int nt = 0; nt < 4; nt++)
                        asm volatile(
                            "mma.sync.aligned.m16n8k8.row.col.f32.tf32.tf32.f32 "
                            "{%0,%1,%2,%3}, {%4,%5,%6,%7}, {%8,%9}, {%0,%1,%2,%3};"
                            : "+f"(c[m0i][mt][nt][0]), "+f"(c[m0i][mt][nt][1]),
                              "+f"(c[m0i][mt][nt][2]), "+f"(c[m0i][mt][nt][3])
                            : "r"(a[mt][0]), "r"(a[mt][1]), "r"(a[mt][2]), "r"(a[mt][3]),
                              "r"(bb[nt][0]), "r"(bb[nt][1]));
            }
        }
        __syncthreads();
    }

    const int gid = lane >> 2;
    const int tig = lane & 3;
    #pragma unroll
    for (int m0i = 0; m0i < 3; m0i++) {
        #pragma unroll
        for (int mt = 0; mt < 2; mt++) {
            #pragma unroll
            for (int half = 0; half < 2; half++) {
                const int ko = m0i * 64 + wm + mt * 16 + half * 8 + gid;
                const int k  = ko >> 6;
                const int o  = ko & 63;
                __half* __restrict__ dst =
                    g_yT + ((size_t)b * TO_ + t * OUT_ + o) * KJP_ + (size_t)k * N_;
                #pragma unroll
                for (int nt = 0; nt < 4; nt++) {
                    const int j = j0 + wn + nt * 8 + tig * 2;
                    if (j < N_) {
                        __half2 v;
                        v.x = __float2half_rn(c[m0i][mt][nt][half * 2 + 0]);
                        v.y = __float2half_rn(c[m0i][mt][nt][half * 2 + 1]);
                        *(__half2*)&dst[j] = v;
                    }
                }
            }
        }
    }
}

// ---------------------------------------------------------------------------
// Kernel 2: A[b][kj][i] = fp16( cheb[kj,i] * SAtt[b, kj%1000, i] )
// NATURAL LAYOUT — pure elementwise, fully coalesced, no smem, no sync.
// ---------------------------------------------------------------------------
__global__ __launch_bounds__(256) void k_buildA2(
    const float* __restrict__ SAtt,
    const float* __restrict__ cheb)
{
    const int b   = blockIdx.y;
    const int kj0 = blockIdx.x * 8;

    for (int idx = threadIdx.x; idx < 8 * 500; idx += 256) {
        const int r  = idx / 500;
        const int i2 = (idx - r * 500) * 2;
        const int kj = kj0 + r;
        const int k  = (kj >= 2000) ? 2 : (kj >= 1000 ? 1 : 0);
        const int j  = kj - k * 1000;

        const float2 cv = *(const float2*)&cheb[(size_t)kj * N_ + i2];
        const float2 sv = *(const float2*)&SAtt[((size_t)b * N_ + j) * N_ + i2];
        __half2 hv;
        hv.x = __float2half_rn(cv.x * sv.x);
        hv.y = __float2half_rn(cv.y * sv.y);
        *(__half2*)&g_AT[((size_t)b * KJP_ + kj) * MP_ + i2] = hv;
    }
}

// ---------------------------------------------------------------------------
// Kernel 3: spatial GEMM, fp16 m16n8k16, CTA 128x128, 256 thr / 8 warps,
// warp tile 64x32, BK=64, 3-stage cp.async ring, 2 CTAs/SM.
// A consumed from k-major [kj][i] layout via ldmatrix.x4.trans.
//   D[b][i][to] = relu( sum_kj A[b][kj][i] * yT[b][to][kj] )
// ---------------------------------------------------------------------------
#define SBK    64
#define NTILE  (KJP_ / SBK)          // 47
#define BNX    128
#define AROW   136                   // halfs per A smem row (272B: conflict-free)
#define BROW   72                    // halfs per B smem row (144B)
#define A_STGH (SBK * AROW)          // 8704 halfs = 17408 B
#define B_STGH (BNX * BROW)          // 9216 halfs = 18432 B
#define STG3   3

__global__ __launch_bounds__(256, 2) void k_spatial_tr(float* __restrict__ out)
{
    extern __shared__ __half sm[];
    __half* Asm = sm;                        // [3][64 kj][136 i]
    __half* Bsm = sm + STG3 * A_STGH;        // [3][128 n][72 k]

    const int b  = blockIdx.z;
    const int i0 = blockIdx.y * 128;
    const int n0 = blockIdx.x * BNX;

    const int tid  = threadIdx.x;
    const int lane = tid & 31;
    const int w    = tid >> 5;            // 0..7
    const int im   = (w & 1) * 64;        // 2 m-strips
    const int in_  = (w >> 1) * 32;       // 4 n-strips

    const __half* __restrict__ pA = g_AT + (size_t)b * KJP_ * MP_ + i0;  // row=kj
    const __half* __restrict__ pB = g_yT + ((size_t)b * TO_ + n0) * KJP_;

    float c[4][4][4];
    #pragma unroll
    for (int mt = 0; mt < 4; mt++)
        #pragma unroll
        for (int nt = 0; nt < 4; nt++)
            #pragma unroll
            for (int q = 0; q < 4; q++) c[mt][nt][q] = 0.f;

    const uint32_t as_base = smem_u32(Asm);
    const uint32_t bs_base = smem_u32(Bsm);

    // trans-A fragment geometry: lane -> (k-row, m-col) of 8x8 tiles
    const int a_krow = (lane & 7) + ((lane >> 4) << 3);   // 0..15
    const int a_mcol = ((lane >> 3) & 1) * 8;             // 0 or 8
    // B fragment geometry (proven)
    const int b_row = (lane & 7) + ((lane & 16) >> 1);
    const int b_k8  = (lane >> 3) & 1;

    #define LOAD_TILE(p, s) do {                                                \
        const uint32_t ao = as_base + (uint32_t)((s) * A_STGH * 2);             \
        const uint32_t bo = bs_base + (uint32_t)((s) * B_STGH * 2);             \
        _Pragma("unroll")                                                       \
        for (int l = 0; l < 4; l++) {   /* A: 64 rows x 128 halfs */            \
            const int cA   = tid + l * 256;                                     \
            const int rowA = cA >> 4;                                           \
            const int colA = (cA & 15) * 8;                                     \
            cpasync16(ao + (uint32_t)((rowA * AROW + colA) * 2),                \
                      pA + (size_t)((p) + rowA) * MP_ + colA);                  \
        }                                                                       \
        _Pragma("unroll")                                                       \
        for (int l = 0; l < 4; l++) {   /* B: 128 rows x 64 halfs */            \
            const int cB   = tid + l * 256;                                     \
            const int rowB = cB >> 3;                                           \
            const int colB = (cB & 7) * 8;                                      \
            cpasync16(bo + (uint32_t)((rowB * BROW + colB) * 2),                \
                      pB + (size_t)rowB * KJP_ + (p) + colB);                   \
        }                                                                       \
        asm volatile("cp.async.commit_group;");                                 \
    } while (0)

    // prologue: tiles 0,1
    LOAD_TILE(0, 0);
    LOAD_TILE(SBK, 1);

    for (int pc = 0; pc < NTILE; pc++) {
        const int cur = pc % STG3;

        if (pc < NTILE - 1) asm volatile("cp.async.wait_group 1;");
        else                asm volatile("cp.async.wait_group 0;");
        __syncthreads();

        if (pc + 2 < NTILE) LOAD_TILE((pc + 2) * SBK, (pc + 2) % STG3);

        const uint32_t sA = as_base + (uint32_t)(cur * A_STGH * 2);
        const uint32_t sB = bs_base + (uint32_t)(cur * B_STGH * 2);

        #pragma unroll
        for (int ks = 0; ks < 4; ks++) {
            const int kb = ks * 16;

            uint32_t a[4][4];
            #pragma unroll
            for (int mt = 0; mt < 4; mt++) {
                const uint32_t off = (uint32_t)(
                    ((kb + a_krow) * AROW + im + mt * 16 + a_mcol) * 2);
                asm volatile(
                    "ldmatrix.sync.aligned.m8n8.x4.trans.shared.b16 "
                    "{%0,%1,%2,%3}, [%4];"
                    : "=r"(a[mt][0]), "=r"(a[mt][1]), "=r"(a[mt][2]), "=r"(a[mt][3])
                    : "r"(sA + off));
            }
            uint32_t bb[4][2];
            #pragma unroll
            for (int nb = 0; nb < 2; nb++) {
                const uint32_t off = (uint32_t)(
                    ((in_ + nb * 16 + b_row) * BROW + kb + b_k8 * 8) * 2);
                uint32_t r0, r1, r2, r3;
                asm volatile(
                    "ldmatrix.sync.aligned.m8n8.x4.shared.b16 {%0,%1,%2,%3}, [%4];"
                    : "=r"(r0), "=r"(r1), "=r"(r2), "=r"(r3)
                    : "r"(sB + off));
                bb[nb * 2][0] = r0;     bb[nb * 2][1] = r1;
                bb[nb * 2 + 1][0] = r2; bb[nb * 2 + 1][1] = r3;
            }
            #pragma unroll
            for (int mt = 0; mt < 4; mt++)
                #pragma unroll
                for (int nt = 0; nt < 4; nt++)
                    asm volatile(
                        "mma.sync.aligned.m16n8k16.row.col.f32.f16.f16.f32 "
                        "{%0,%1,%2,%3}, {%4,%5,%6,%7}, {%8,%9}, {%0,%1,%2,%3};"
                        : "+f"(c[mt][nt][0]), "+f"(c[mt][nt][1]),
                          "+f"(c[mt][nt][2]), "+f"(c[mt][nt][3])
                        : "r"(a[mt][0]), "r"(a[mt][1]), "r"(a[mt][2]), "r"(a[mt][3]),
                          "r"(bb[nt][0]), "r"(bb[nt][1]));
        }
        // no trailing sync; next iteration's barrier protects stage reuse
    }

    // Epilogue with fused relu. Warp n-extent 32, 32-aligned -> t const.
    const int gid = lane >> 2;
    const int tig = lane & 3;
    const int t   = (n0 + in_) >> 6;
    const int o0  = (n0 + in_) & 63;
    #pragma unroll
    for (int mt = 0; mt < 4; mt++) {
        #pragma unroll
        for (int half = 0; half < 2; half++) {
            const int i = i0 + im + mt * 16 + half * 8 + gid;
            if (i < N_) {
                float* __restrict__ dst =
                    out + (size_t)b * (T_ * N_ * OUT_) + (size_t)t * (N_ * OUT_) +
                    (size_t)i * OUT_ + o0;
                #pragma unroll
                for (int nt = 0; nt < 4; nt++) {
                    const int o = nt * 8 + tig * 2;
                    float2 v;
                    v.x = fmaxf(c[mt][nt][half * 2 + 0], 0.f);
                    v.y = fmaxf(c[mt][nt][half * 2 + 1], 0.f);
                    *(float2*)&dst[o] = v;
                }
            }
        }
    }
}

// ---------------------------------------------------------------------------
// Launch
// ---------------------------------------------------------------------------
extern "C" void kernel_launch(void* const* d_in, const int* in_sizes, int n_in,
                              void* d_out, int out_size)
{
    const float* x     = (const float*)d_in[0];
    const float* SAtt  = (const float*)d_in[1];
    const float* cheb  = (const float*)d_in[2];
    const float* Theta = (const float*)d_in[3];
    float* out = (float*)d_out;

    const int smem_sp = STG3 * (A_STGH + B_STGH) * 2;   // 107520 B
    cudaFuncSetAttribute(k_spatial_tr,
                         cudaFuncAttributeMaxDynamicSharedMemorySize, smem_sp);

    k_thetaT<<<1, 256>>>(Theta);
    k_featT_m<<<dim3(8, B_ * T_), 256>>>(x);
    k_buildA2<<<dim3(KJ_ / 8, B_), 256>>>(SAtt, cheb);
    k_spatial_tr<<<dim3(TO_ / BNX, MP_ / 128, B_), 256, smem_sp>>>(out);
}